// round 6
// baseline (speedup 1.0000x reference)
#include <cuda_runtime.h>
#include <cstdint>

// trans_b: [32, 64, 256, 256] fp32 = 32 batches x 64 planes x 16384 float4
#define NBATCH        32
#define NBLOCKS       512
#define NTHREADS      512
#define UNIT_F4       4096          // 64 KB units (quarter plane)
#define POOL_TOTAL    8192          // 2048 planes * 4 quarters
#define UNITS_PER_B   256           // pool/scale units per batch
#define SCALE_PER_B   256

__device__ float    g_partial[POOL_TOTAL];   // per-quarter sums (written once)
__device__ float    g_scale[2048];           // per-plane scale
__device__ unsigned g_pticket;               // global pool ticket
__device__ unsigned g_sticket[NBATCH];       // per-batch scale tickets
__device__ unsigned g_pdone[NBATCH];         // pool units completed per batch
__device__ unsigned g_ready[NBATCH];         // scale factors published
__device__ unsigned g_cnt, g_gen;            // entry barrier (replay-safe)

__device__ __forceinline__ void entry_barrier()
{
    __syncthreads();
    if (threadIdx.x == 0) {
        unsigned gen = atomicAdd(&g_gen, 0u);
        if (atomicAdd(&g_cnt, 1u) == NBLOCKS - 1u) {
            atomicExch(&g_cnt, 0u);
            __threadfence();
            atomicAdd(&g_gen, 1u);
        } else {
            while (atomicAdd(&g_gen, 0u) == gen) __nanosleep(32);
        }
        __threadfence();
    }
    __syncthreads();
}

__global__ void __launch_bounds__(NTHREADS, 4) se_pipeline_kernel(
    const float* __restrict__ x, float* __restrict__ y,
    const float* __restrict__ w_down,  // [4,64]
    const float* __restrict__ b_down,  // [4]
    const float* __restrict__ w_up,    // [64,4]
    const float* __restrict__ b_up)    // [64]
{
    const int tid = threadIdx.x;
    const float4* __restrict__ px = reinterpret_cast<const float4*>(x);
    float4*       __restrict__ py = reinterpret_cast<float4*>(y);

    __shared__ float    sred[16];
    __shared__ float    sp[64];     // pooled means (MLP scratch)
    __shared__ float    sh[4];      // relu hidden
    __shared__ unsigned s_u;
    __shared__ int      s_kind;     // 0=pool 1=scale 2=exit
    __shared__ int      s_last;
    __shared__ int      s_bhint;    // lowest possibly-claimable scale batch

    // Per-launch counter resets (block 0), published before the barrier.
    if (blockIdx.x == 0) {
        if (tid == 0) g_pticket = 0u;
        if (tid < NBATCH) {
            g_sticket[tid] = 0u;
            g_pdone[tid]   = 0u;
            g_ready[tid]   = 0u;
        }
        __threadfence();
    }
    if (tid == 0) s_bhint = 0;
    entry_barrier();

    for (;;) {
        // ---------------- work selection (tid 0) -------------------------
        if (tid == 0) {
            int kind = -1;
            unsigned u = 0;
            while (kind < 0) {
                // Prefer scale on the lowest ready batch (keeps L2 lag ~1 batch).
                int b = s_bhint;
                for (; b < NBATCH; b++) {
                    if (atomicAdd(&g_ready[b], 0u) == 0u) break;   // later b not ready yet (typ.)
                    if (atomicAdd(&g_sticket[b], 0u) < SCALE_PER_B) {
                        unsigned t = atomicAdd(&g_sticket[b], 1u);
                        if (t < SCALE_PER_B) { u = (unsigned)b * SCALE_PER_B + t; kind = 1; }
                        break;
                    } else if (b == s_bhint) {
                        s_bhint = b + 1;            // batch fully claimed
                    }
                }
                if (kind >= 0) break;
                // Fall back to pool.
                if (atomicAdd(&g_pticket, 0u) < POOL_TOTAL) {
                    unsigned p = atomicAdd(&g_pticket, 1u);
                    if (p < POOL_TOTAL) { u = p; kind = 0; }
                } else if (s_bhint >= NBATCH) {
                    kind = 2;                       // everything claimed -> exit
                } else {
                    __nanosleep(128);               // tail: wait for ready flip
                }
            }
            if (kind == 1) __threadfence();         // acquire for g_scale read
            s_u = u; s_kind = kind;
        }
        __syncthreads();
        const unsigned u = s_u;
        const int kind = s_kind;
        __syncthreads();                            // s_u/s_kind reusable

        if (kind == 2) break;

        if (kind == 0) {
            // ---------------- pool one 64 KB quarter-plane ----------------
            const size_t base = (size_t)u << 12;    // u * 4096 f4
            float a0 = 0.0f, a1 = 0.0f;
            #pragma unroll
            for (int i = 0; i < 8; i += 2) {
                float4 v = __ldcg(px + base + tid + (size_t)i * NTHREADS);
                float4 w = __ldcg(px + base + tid + (size_t)(i + 1) * NTHREADS);
                a0 += (v.x + v.y) + (v.z + v.w);
                a1 += (w.x + w.y) + (w.z + w.w);
            }
            float sum = a0 + a1;
            #pragma unroll
            for (int o = 16; o > 0; o >>= 1)
                sum += __shfl_xor_sync(0xFFFFFFFFu, sum, o);
            if ((tid & 31) == 0) sred[tid >> 5] = sum;
            __syncthreads();
            if (tid == 0) {
                float t = 0.0f;
                #pragma unroll
                for (int j = 0; j < 16; j++) t += sred[j];
                __stcg(&g_partial[u], t);
                __threadfence();
                unsigned old = atomicAdd(&g_pdone[u >> 8], 1u);
                s_last = (old == UNITS_PER_B - 1u);
            }
            __syncthreads();

            if (s_last) {
                // This block completed batch b's pooling: inline MLP.
                const int b = u >> 8;
                if (tid == 0) __threadfence();      // see all partials
                __syncthreads();
                if (tid < 64) {
                    const float* pp = g_partial + ((size_t)(b * 64 + tid) << 2);
                    sp[tid] = ((__ldcg(pp + 0) + __ldcg(pp + 1)) +
                               (__ldcg(pp + 2) + __ldcg(pp + 3))) * (1.0f / 65536.0f);
                }
                __syncthreads();
                if (tid < 4) {
                    float h = b_down[tid];
                    #pragma unroll 8
                    for (int k = 0; k < 64; k++)
                        h = fmaf(sp[k], __ldg(&w_down[tid * 64 + k]), h);
                    sh[tid] = fmaxf(h, 0.0f);
                }
                __syncthreads();
                if (tid < 64) {
                    float s = b_up[tid];
                    #pragma unroll
                    for (int m = 0; m < 4; m++)
                        s = fmaf(sh[m], __ldg(&w_up[tid * 4 + m]), s);
                    __stcg(&g_scale[b * 64 + tid], 1.0f / (1.0f + expf(-s)));
                    __threadfence();
                }
                __syncthreads();
                if (tid == 0) atomicExch(&g_ready[b], 1u);
            }
        } else {
            // ---------------- scale one 64 KB quarter-plane ---------------
            const size_t base = (size_t)u << 12;
            const float s = __ldcg(&g_scale[u >> 2]);
            #pragma unroll
            for (int i = 0; i < 8; i++) {
                const size_t idx = base + tid + (size_t)i * NTHREADS;
                float4 v = __ldcg(px + idx);        // L2 hit: pooled ~1 batch ago
                v.x *= s; v.y *= s; v.z *= s; v.w *= s;
                __stcs(py + idx, v);                // evict-first stores
            }
        }
    }
}

extern "C" void kernel_launch(void* const* d_in, const int* in_sizes, int n_in,
                              void* d_out, int out_size)
{
    const float* trans_b = (const float*)d_in[0];
    const float* w_down  = (const float*)d_in[1];
    const float* b_down  = (const float*)d_in[2];
    const float* w_up    = (const float*)d_in[3];
    const float* b_up    = (const float*)d_in[4];
    float* out = (float*)d_out;

    se_pipeline_kernel<<<NBLOCKS, NTHREADS>>>(trans_b, out, w_down, b_down, w_up, b_up);
}